// round 1
// baseline (speedup 1.0000x reference)
#include <cuda_runtime.h>
#include <math.h>
#include <stdint.h>

// Problem constants
#define N_HEADS 16
#define D_MODEL 1024
#define D_HEAD  64
#define BATCH   2
#define SEQ     2048
#define ROWS    (BATCH*SEQ)          // 4096
#define QKV_N   (3*N_HEADS*D_HEAD)   // 3072

// ---------------- device scratch (no allocations allowed) ----------------
__device__ float g_wt[D_MODEL * QKV_N];     // [m, which*1024 + h*64 + d]  12 MB
__device__ float g_bias[QKV_N];             // packed bQ|bK|bV
__device__ float g_qkv[(size_t)ROWS * QKV_N]; // 48 MB
__device__ float g_z[(size_t)ROWS * D_MODEL]; // 16 MB

// ---------------- weight / bias packing ----------------
__global__ void pack_w_kernel(const float* __restrict__ Wq,
                              const float* __restrict__ Wk,
                              const float* __restrict__ Wv) {
    int idx = blockIdx.x * 256 + threadIdx.x;   // enumerates (which,h,m,d)
    const int total = 3 * N_HEADS * D_MODEL * D_HEAD; // 3*2^20
    if (idx >= total) return;
    int d = idx & 63;
    int m = (idx >> 6) & 1023;
    int h = (idx >> 16) & 15;
    int which = idx >> 20;
    const float* W = (which == 0) ? Wq : (which == 1) ? Wk : Wv;
    float v = W[idx & ((1 << 20) - 1)];       // h*65536 + m*64 + d
    g_wt[(size_t)m * QKV_N + which * 1024 + h * 64 + d] = v;
}

__global__ void pack_bias_kernel(const float* __restrict__ bq,
                                 const float* __restrict__ bk,
                                 const float* __restrict__ bv) {
    int i = blockIdx.x * 256 + threadIdx.x;
    if (i >= QKV_N) return;
    float v;
    if (i < 1024) v = bq[i];
    else if (i < 2048) v = bk[i - 1024];
    else v = bv[i - 2048];
    g_bias[i] = v;
}

// ---------------- tiled fp32 GEMM: C[M,N] = A[M,K]*B[K,N] + bias[N] ----------------
#define GBM 128
#define GBN 128
#define GBK 16
#define GTM 8
#define GTN 8

__global__ __launch_bounds__(256)
void sgemm_bias_kernel(const float* __restrict__ A, const float* __restrict__ B,
                       float* __restrict__ C, const float* __restrict__ bias,
                       int M, int N, int K) {
    __shared__ float As[GBK][GBM];
    __shared__ float Bs[GBK][GBN + 4];

    int tid = threadIdx.x;
    int br = blockIdx.y, bc = blockIdx.x;
    const float* Ablk = A + (size_t)br * GBM * K;
    const float* Bblk = B + (size_t)bc * GBN;

    int arow  = tid >> 2;           // 0..63 (handles r, r+64)
    int acol4 = (tid & 3) << 2;     // 0,4,8,12
    int brow  = tid >> 5;           // 0..7 (handles r, r+8)
    int bcol4 = (tid & 31) << 2;    // 0..124
    int trow  = (tid >> 4) * GTM;
    int tcol  = (tid & 15) * GTN;

    float acc[GTM][GTN];
#pragma unroll
    for (int i = 0; i < GTM; i++)
#pragma unroll
        for (int j = 0; j < GTN; j++) acc[i][j] = 0.f;

    for (int k0 = 0; k0 < K; k0 += GBK) {
#pragma unroll
        for (int i = 0; i < 2; i++) {
            int r = arow + i * 64;
            float4 v = *(const float4*)(Ablk + (size_t)r * K + k0 + acol4);
            As[acol4 + 0][r] = v.x;
            As[acol4 + 1][r] = v.y;
            As[acol4 + 2][r] = v.z;
            As[acol4 + 3][r] = v.w;
        }
#pragma unroll
        for (int i = 0; i < 2; i++) {
            int r = brow + i * 8;
            float4 v = *(const float4*)(Bblk + (size_t)(k0 + r) * N + bcol4);
            Bs[r][bcol4 + 0] = v.x;
            Bs[r][bcol4 + 1] = v.y;
            Bs[r][bcol4 + 2] = v.z;
            Bs[r][bcol4 + 3] = v.w;
        }
        __syncthreads();

#pragma unroll
        for (int kk = 0; kk < GBK; kk++) {
            float ra[GTM], rb[GTN];
#pragma unroll
            for (int i = 0; i < GTM; i++) ra[i] = As[kk][trow + i];
#pragma unroll
            for (int j = 0; j < GTN; j++) rb[j] = Bs[kk][tcol + j];
#pragma unroll
            for (int i = 0; i < GTM; i++)
#pragma unroll
                for (int j = 0; j < GTN; j++)
                    acc[i][j] += ra[i] * rb[j];
        }
        __syncthreads();
    }

#pragma unroll
    for (int i = 0; i < GTM; i++) {
        size_t row = (size_t)br * GBM + trow + i;
#pragma unroll
        for (int j = 0; j < GTN; j += 4) {
            int col = bc * GBN + tcol + j;
            float4 v;
            v.x = acc[i][j + 0] + bias[col + 0];
            v.y = acc[i][j + 1] + bias[col + 1];
            v.z = acc[i][j + 2] + bias[col + 2];
            v.w = acc[i][j + 3] + bias[col + 3];
            *(float4*)(C + row * N + col) = v;
        }
    }
}

// ---------------- flash attention (causal), fp32 ----------------
// grid: (SEQ/64, N_HEADS, BATCH), 256 threads, dynamic smem 4*64*65*4 bytes
#define FST 65   // smem row stride (pad 1 -> only 2-way conflicts)
#define QS(r,c) Qs[(r)*FST + (c)]
#define KS(r,c) Ks[(r)*FST + (c)]
#define VS(r,c) Vs[(r)*FST + (c)]
#define PS(r,c) Ps[(r)*FST + (c)]

__global__ __launch_bounds__(256)
void flash_kernel(const float* __restrict__ qkv, float* __restrict__ z) {
    extern __shared__ float sm[];
    float* Qs = sm;                  // 64 x 65
    float* Ks = Qs + 64 * FST;
    float* Vs = Ks + 64 * FST;
    float* Ps = Vs + 64 * FST;

    int tid = threadIdx.x;
    int qb = blockIdx.x, h = blockIdx.y, b = blockIdx.z;
    int ty = tid >> 4, tx = tid & 15;

    const float* base = qkv + ((size_t)b * SEQ) * QKV_N + h * D_HEAD;
    const float* qptr = base + (size_t)(qb * 64) * QKV_N;          // Q columns

    // load Q tile [64 x 64]
    for (int t = tid; t < 64 * 16; t += 256) {
        int r = t >> 4, c = (t & 15) << 2;
        float4 v = *(const float4*)(qptr + (size_t)r * QKV_N + c);
        QS(r, c) = v.x; QS(r, c + 1) = v.y; QS(r, c + 2) = v.z; QS(r, c + 3) = v.w;
    }

    float acc[4][4];
    float mrun[4], lrun[4];
#pragma unroll
    for (int i = 0; i < 4; i++) {
        mrun[i] = -1e30f; lrun[i] = 0.f;
#pragma unroll
        for (int j = 0; j < 4; j++) acc[i][j] = 0.f;
    }

    const float scale = 0.125f;  // 1/sqrt(64)

    for (int jb = 0; jb <= qb; jb++) {
        __syncthreads();   // previous PV done / Q loaded before K/V overwrite
        const float* kptr = base + (size_t)(jb * 64) * QKV_N + 1024;
        const float* vptr = base + (size_t)(jb * 64) * QKV_N + 2048;
        for (int t = tid; t < 64 * 16; t += 256) {
            int r = t >> 4, c = (t & 15) << 2;
            float4 kv = *(const float4*)(kptr + (size_t)r * QKV_N + c);
            KS(r, c) = kv.x; KS(r, c + 1) = kv.y; KS(r, c + 2) = kv.z; KS(r, c + 3) = kv.w;
            float4 vv = *(const float4*)(vptr + (size_t)r * QKV_N + c);
            VS(r, c) = vv.x; VS(r, c + 1) = vv.y; VS(r, c + 2) = vv.z; VS(r, c + 3) = vv.w;
        }
        __syncthreads();

        // S = Q K^T, 4x4 per thread
        float s[4][4];
#pragma unroll
        for (int i = 0; i < 4; i++)
#pragma unroll
            for (int j = 0; j < 4; j++) s[i][j] = 0.f;

        for (int k = 0; k < 64; k++) {
            float qa[4], kb[4];
#pragma unroll
            for (int i = 0; i < 4; i++) qa[i] = QS(4 * ty + i, k);
#pragma unroll
            for (int j = 0; j < 4; j++) kb[j] = KS(4 * tx + j, k);
#pragma unroll
            for (int i = 0; i < 4; i++)
#pragma unroll
                for (int j = 0; j < 4; j++) s[i][j] += qa[i] * kb[j];
        }
#pragma unroll
        for (int i = 0; i < 4; i++)
#pragma unroll
            for (int j = 0; j < 4; j++) s[i][j] *= scale;

        if (jb == qb) {
#pragma unroll
            for (int i = 0; i < 4; i++)
#pragma unroll
                for (int j = 0; j < 4; j++)
                    if (4 * tx + j > 4 * ty + i) s[i][j] = -INFINITY;
        }

        // online softmax: row groups are the 16 tx-lanes (contiguous half-warp)
        float mloc[4];
#pragma unroll
        for (int i = 0; i < 4; i++) {
            mloc[i] = fmaxf(fmaxf(s[i][0], s[i][1]), fmaxf(s[i][2], s[i][3]));
#pragma unroll
            for (int off = 8; off >= 1; off >>= 1)
                mloc[i] = fmaxf(mloc[i], __shfl_xor_sync(0xffffffffu, mloc[i], off));
        }

        float fac[4], lsum[4];
#pragma unroll
        for (int i = 0; i < 4; i++) {
            float mnew = fmaxf(mrun[i], mloc[i]);
            fac[i] = __expf(mrun[i] - mnew);
            mrun[i] = mnew;
            lsum[i] = 0.f;
#pragma unroll
            for (int j = 0; j < 4; j++) {
                float p = __expf(s[i][j] - mnew);
                PS(4 * ty + i, 4 * tx + j) = p;
                lsum[i] += p;
            }
#pragma unroll
            for (int off = 8; off >= 1; off >>= 1)
                lsum[i] += __shfl_xor_sync(0xffffffffu, lsum[i], off);
            lrun[i] = lrun[i] * fac[i] + lsum[i];
#pragma unroll
            for (int j = 0; j < 4; j++) acc[i][j] *= fac[i];
        }
        __syncthreads();

        // O += P @ V
        for (int k = 0; k < 64; k++) {
            float pv[4], vv[4];
#pragma unroll
            for (int i = 0; i < 4; i++) pv[i] = PS(4 * ty + i, k);
#pragma unroll
            for (int j = 0; j < 4; j++) vv[j] = VS(k, 4 * tx + j);
#pragma unroll
            for (int i = 0; i < 4; i++)
#pragma unroll
                for (int j = 0; j < 4; j++) acc[i][j] += pv[i] * vv[j];
        }
    }

    // write z[b, q, h, d]
#pragma unroll
    for (int i = 0; i < 4; i++) {
        size_t row = (size_t)b * SEQ + qb * 64 + 4 * ty + i;
        float inv_l = 1.0f / lrun[i];
#pragma unroll
        for (int j = 0; j < 4; j++) {
            z[row * D_MODEL + h * D_HEAD + 4 * tx + j] = acc[i][j] * inv_l;
        }
    }
}

// ---------------- launch ----------------
extern "C" void kernel_launch(void* const* d_in, const int* in_sizes, int n_in,
                              void* d_out, int out_size) {
    const float* x   = (const float*)d_in[0];
    const float* Wq  = (const float*)d_in[1];
    const float* Wk  = (const float*)d_in[2];
    const float* Wv  = (const float*)d_in[3];
    const float* Wo  = (const float*)d_in[4];   // [h,d,m] == [1024,1024] row-major (k=h*64+d, n=m)
    const float* bq  = (const float*)d_in[5];
    const float* bk  = (const float*)d_in[6];
    const float* bv  = (const float*)d_in[7];
    const float* bo  = (const float*)d_in[8];
    float* out = (float*)d_out;

    float *wt, *bias, *qkv, *zbuf;
    cudaGetSymbolAddress((void**)&wt,   g_wt);
    cudaGetSymbolAddress((void**)&bias, g_bias);
    cudaGetSymbolAddress((void**)&qkv,  g_qkv);
    cudaGetSymbolAddress((void**)&zbuf, g_z);

    // 1. pack weights / biases
    {
        int total = 3 * N_HEADS * D_MODEL * D_HEAD;
        pack_w_kernel<<<(total + 255) / 256, 256>>>(Wq, Wk, Wv);
        pack_bias_kernel<<<(QKV_N + 255) / 256, 256>>>(bq, bk, bv);
    }

    // 2. QKV projection: [4096,1024] x [1024,3072]
    {
        dim3 grid(QKV_N / GBN, ROWS / GBM);
        sgemm_bias_kernel<<<grid, 256>>>(x, wt, qkv, bias, ROWS, QKV_N, D_MODEL);
    }

    // 3. flash attention
    {
        int smem = 4 * 64 * FST * (int)sizeof(float);  // 66560
        cudaFuncSetAttribute(flash_kernel, cudaFuncAttributeMaxDynamicSharedMemorySize, smem);
        dim3 grid(SEQ / 64, N_HEADS, BATCH);
        flash_kernel<<<grid, 256, smem>>>(qkv, zbuf);
    }

    // 4. output projection: [4096,1024] x [1024,1024] + b_O
    {
        dim3 grid(D_MODEL / GBN, ROWS / GBM);
        sgemm_bias_kernel<<<grid, 256>>>(zbuf, Wo, out, bo, ROWS, D_MODEL, D_MODEL);
    }
}

// round 2
// speedup vs baseline: 2.5749x; 2.5749x over previous
#include <cuda_runtime.h>
#include <math.h>
#include <stdint.h>

#define N_HEADS 16
#define D_MODEL 1024
#define D_HEAD  64
#define BATCH   2
#define SEQ     2048
#define ROWS    (BATCH*SEQ)          // 4096
#define QKV_N   (3*N_HEADS*D_HEAD)   // 3072

// ---------------- device scratch ----------------
__device__ float g_wt[D_MODEL * QKV_N];       // packed [m][which*1024 + h*64 + d]
__device__ float g_bias[QKV_N];
__device__ float g_qkv[(size_t)ROWS * QKV_N];
__device__ float g_z[(size_t)ROWS * D_MODEL];

// ---------------- helpers ----------------
__device__ __forceinline__ uint32_t f2tf32(float f) {
    uint32_t u;
    asm("cvt.rna.tf32.f32 %0, %1;" : "=r"(u) : "f"(f));
    return u;
}

__device__ __forceinline__ void mma_tf32(float* c,
                                         uint32_t a0, uint32_t a1, uint32_t a2, uint32_t a3,
                                         uint32_t b0, uint32_t b1) {
    asm volatile(
        "mma.sync.aligned.m16n8k8.row.col.f32.tf32.tf32.f32 "
        "{%0,%1,%2,%3}, {%4,%5,%6,%7}, {%8,%9}, {%0,%1,%2,%3};"
        : "+f"(c[0]), "+f"(c[1]), "+f"(c[2]), "+f"(c[3])
        : "r"(a0), "r"(a1), "r"(a2), "r"(a3), "r"(b0), "r"(b1));
}

// ---------------- weight / bias packing ----------------
__global__ void pack_w_kernel(const float* __restrict__ Wq,
                              const float* __restrict__ Wk,
                              const float* __restrict__ Wv) {
    int idx = blockIdx.x * 256 + threadIdx.x;
    const int total = 3 * N_HEADS * D_MODEL * D_HEAD;
    if (idx >= total) return;
    int d = idx & 63;
    int m = (idx >> 6) & 1023;
    int h = (idx >> 16) & 15;
    int which = idx >> 20;
    const float* W = (which == 0) ? Wq : (which == 1) ? Wk : Wv;
    float v = W[idx & ((1 << 20) - 1)];
    g_wt[(size_t)m * QKV_N + which * 1024 + h * 64 + d] = v;
}

__global__ void pack_bias_kernel(const float* __restrict__ bq,
                                 const float* __restrict__ bk,
                                 const float* __restrict__ bv) {
    int i = blockIdx.x * 256 + threadIdx.x;
    if (i >= QKV_N) return;
    float v;
    if (i < 1024) v = bq[i];
    else if (i < 2048) v = bk[i - 1024];
    else v = bv[i - 2048];
    g_bias[i] = v;
}

// ---------------- tf32 tensor-core GEMM: C = A[M,K]*B[K,N] + bias ----------------
#define TBM 128
#define TBN 128
#define TBK 16
#define TST 132   // padded smem row stride (floats)

__global__ __launch_bounds__(256)
void tf32_gemm_bias(const float* __restrict__ A, const float* __restrict__ B,
                    float* __restrict__ C, const float* __restrict__ bias,
                    int M, int N, int K) {
    __shared__ uint32_t As[2][TBK][TST];   // [k][m]
    __shared__ uint32_t Bs[2][TBK][TST];   // [k][n]

    const int tid  = threadIdx.x;
    const int lane = tid & 31;
    const int warp = tid >> 5;
    const int gid  = lane >> 2;
    const int tig  = lane & 3;
    const int wm   = (warp >> 2) * 64;   // 0 / 64
    const int wn   = (warp & 3) * 32;    // 0..96
    const int br   = blockIdx.y, bc = blockIdx.x;

    const float* Ab = A + (size_t)br * TBM * K;
    const float* Bb = B + (size_t)bc * TBN;

    const int a_m = tid >> 2;            // 0..63 (+64)
    const int a_k = (tid & 3) << 2;      // 0,4,8,12
    const int b_r = tid >> 5;            // 0..7 (+8)
    const int b_c = (tid & 31) << 2;     // 0..124

    float acc[4][4][4];
#pragma unroll
    for (int mt = 0; mt < 4; mt++)
#pragma unroll
        for (int nt = 0; nt < 4; nt++)
#pragma unroll
            for (int e = 0; e < 4; e++) acc[mt][nt][e] = 0.f;

    // prologue: tile 0 into buffer 0
    {
#pragma unroll
        for (int h = 0; h < 2; h++) {
            int m = a_m + h * 64;
            float4 v = *(const float4*)(Ab + (size_t)m * K + a_k);
            As[0][a_k + 0][m] = f2tf32(v.x);
            As[0][a_k + 1][m] = f2tf32(v.y);
            As[0][a_k + 2][m] = f2tf32(v.z);
            As[0][a_k + 3][m] = f2tf32(v.w);
        }
#pragma unroll
        for (int h = 0; h < 2; h++) {
            int r = b_r + h * 8;
            float4 v = *(const float4*)(Bb + (size_t)r * N + b_c);
            uint4 u = make_uint4(f2tf32(v.x), f2tf32(v.y), f2tf32(v.z), f2tf32(v.w));
            *(uint4*)&Bs[0][r][b_c] = u;
        }
    }
    __syncthreads();

    const int ntiles = K / TBK;
    for (int t = 0; t < ntiles; t++) {
        const int buf = t & 1;
        float4 pA0, pA1, pB0, pB1;
        if (t + 1 < ntiles) {
            int k0 = (t + 1) * TBK;
            pA0 = *(const float4*)(Ab + (size_t)a_m * K + k0 + a_k);
            pA1 = *(const float4*)(Ab + (size_t)(a_m + 64) * K + k0 + a_k);
            pB0 = *(const float4*)(Bb + (size_t)(k0 + b_r) * N + b_c);
            pB1 = *(const float4*)(Bb + (size_t)(k0 + b_r + 8) * N + b_c);
        }

#pragma unroll
        for (int ks = 0; ks < 2; ks++) {
            const int kk = ks * 8 + tig;
            uint32_t af[4][4], bf[4][2];
#pragma unroll
            for (int mt = 0; mt < 4; mt++) {
                int m0 = wm + mt * 16 + gid;
                af[mt][0] = As[buf][kk][m0];
                af[mt][1] = As[buf][kk][m0 + 8];
                af[mt][2] = As[buf][kk + 4][m0];
                af[mt][3] = As[buf][kk + 4][m0 + 8];
            }
#pragma unroll
            for (int nt = 0; nt < 4; nt++) {
                int n0 = wn + nt * 8 + gid;
                bf[nt][0] = Bs[buf][kk][n0];
                bf[nt][1] = Bs[buf][kk + 4][n0];
            }
#pragma unroll
            for (int mt = 0; mt < 4; mt++)
#pragma unroll
                for (int nt = 0; nt < 4; nt++)
                    mma_tf32(acc[mt][nt], af[mt][0], af[mt][1], af[mt][2], af[mt][3],
                             bf[nt][0], bf[nt][1]);
        }

        if (t + 1 < ntiles) {
            const int nb = buf ^ 1;
            As[nb][a_k + 0][a_m] = f2tf32(pA0.x);
            As[nb][a_k + 1][a_m] = f2tf32(pA0.y);
            As[nb][a_k + 2][a_m] = f2tf32(pA0.z);
            As[nb][a_k + 3][a_m] = f2tf32(pA0.w);
            As[nb][a_k + 0][a_m + 64] = f2tf32(pA1.x);
            As[nb][a_k + 1][a_m + 64] = f2tf32(pA1.y);
            As[nb][a_k + 2][a_m + 64] = f2tf32(pA1.z);
            As[nb][a_k + 3][a_m + 64] = f2tf32(pA1.w);
            uint4 u0 = make_uint4(f2tf32(pB0.x), f2tf32(pB0.y), f2tf32(pB0.z), f2tf32(pB0.w));
            uint4 u1 = make_uint4(f2tf32(pB1.x), f2tf32(pB1.y), f2tf32(pB1.z), f2tf32(pB1.w));
            *(uint4*)&Bs[nb][b_r][b_c] = u0;
            *(uint4*)&Bs[nb][b_r + 8][b_c] = u1;
        }
        __syncthreads();
    }

    // epilogue
#pragma unroll
    for (int mt = 0; mt < 4; mt++) {
        size_t r0 = (size_t)br * TBM + wm + mt * 16 + gid;
        size_t r1 = r0 + 8;
#pragma unroll
        for (int nt = 0; nt < 4; nt++) {
            int col = bc * TBN + wn + nt * 8 + 2 * tig;
            float b0v = bias[col], b1v = bias[col + 1];
            float2 v0 = make_float2(acc[mt][nt][0] + b0v, acc[mt][nt][1] + b1v);
            float2 v1 = make_float2(acc[mt][nt][2] + b0v, acc[mt][nt][3] + b1v);
            *(float2*)(C + r0 * N + col) = v0;
            *(float2*)(C + r1 * N + col) = v1;
        }
    }
}

// ---------------- tf32 tensor-core flash attention (causal) ----------------
#define FSTR 68   // padded smem row stride (u32)

__global__ __launch_bounds__(256)
void flash_tf32_kernel(const float* __restrict__ qkv, float* __restrict__ z) {
    extern __shared__ uint32_t sm[];
    uint32_t* Qs = sm;                    // [128][FSTR]
    uint32_t* Ks = Qs + 128 * FSTR;       // [64][FSTR]
    uint32_t* Vs = Ks + 64 * FSTR;        // [64][FSTR]
    uint32_t* Ps = Vs + 64 * FSTR;        // [128][FSTR]

    const int tid  = threadIdx.x;
    const int lane = tid & 31;
    const int warp = tid >> 5;            // 8 warps, 16 q-rows each
    const int gid  = lane >> 2;
    const int tig  = lane & 3;
    const int qb = blockIdx.x, h = blockIdx.y, b = blockIdx.z;

    const float* base = qkv + (size_t)b * SEQ * QKV_N + h * D_HEAD;
    const float* qptr = base + (size_t)qb * 128 * QKV_N;

    // Q tile 128x64, scaled by 1/sqrt(64)=0.125 (exact), converted to tf32
    for (int t = tid; t < 128 * 16; t += 256) {
        int r = t >> 4, c = (t & 15) << 2;
        float4 v = *(const float4*)(qptr + (size_t)r * QKV_N + c);
        uint4 u = make_uint4(f2tf32(v.x * 0.125f), f2tf32(v.y * 0.125f),
                             f2tf32(v.z * 0.125f), f2tf32(v.w * 0.125f));
        *(uint4*)&Qs[r * FSTR + c] = u;
    }

    float o[8][4];
#pragma unroll
    for (int nt = 0; nt < 8; nt++)
#pragma unroll
        for (int e = 0; e < 4; e++) o[nt][e] = 0.f;
    float mrun0 = -1e30f, mrun1 = -1e30f, lrun0 = 0.f, lrun1 = 0.f;

    const int wrow = warp * 16;
    const int grow = qb * 128 + wrow;
    const int jbmax = (qb * 128 + 127) / 64;

    for (int jb = 0; jb <= jbmax; jb++) {
        __syncthreads();
        const float* kp = base + (size_t)jb * 64 * QKV_N + 1024;
        const float* vp = kp + 1024;
        for (int t = tid; t < 64 * 16; t += 256) {
            int r = t >> 4, c = (t & 15) << 2;
            float4 kv = *(const float4*)(kp + (size_t)r * QKV_N + c);
            *(uint4*)&Ks[r * FSTR + c] =
                make_uint4(f2tf32(kv.x), f2tf32(kv.y), f2tf32(kv.z), f2tf32(kv.w));
            float4 vv = *(const float4*)(vp + (size_t)r * QKV_N + c);
            *(uint4*)&Vs[r * FSTR + c] =
                make_uint4(f2tf32(vv.x), f2tf32(vv.y), f2tf32(vv.z), f2tf32(vv.w));
        }
        __syncthreads();

        bool active = (jb * 64 <= grow + 15);
        if (active) {
            float s[8][4];
#pragma unroll
            for (int nt = 0; nt < 8; nt++)
#pragma unroll
                for (int e = 0; e < 4; e++) s[nt][e] = 0.f;

            // S = Q K^T
#pragma unroll
            for (int ks = 0; ks < 8; ks++) {
                int kk = ks * 8 + tig;
                uint32_t a0 = Qs[(wrow + gid) * FSTR + kk];
                uint32_t a1 = Qs[(wrow + gid + 8) * FSTR + kk];
                uint32_t a2 = Qs[(wrow + gid) * FSTR + kk + 4];
                uint32_t a3 = Qs[(wrow + gid + 8) * FSTR + kk + 4];
#pragma unroll
                for (int nt = 0; nt < 8; nt++) {
                    uint32_t b0 = Ks[(nt * 8 + gid) * FSTR + kk];
                    uint32_t b1 = Ks[(nt * 8 + gid) * FSTR + kk + 4];
                    mma_tf32(s[nt], a0, a1, a2, a3, b0, b1);
                }
            }

            // causal mask
            int r0g = grow + gid, r1g = r0g + 8;
            if (jb * 64 + 63 > grow) {
#pragma unroll
                for (int nt = 0; nt < 8; nt++) {
                    int col = jb * 64 + nt * 8 + 2 * tig;
                    if (col     > r0g) s[nt][0] = -1e30f;
                    if (col + 1 > r0g) s[nt][1] = -1e30f;
                    if (col     > r1g) s[nt][2] = -1e30f;
                    if (col + 1 > r1g) s[nt][3] = -1e30f;
                }
            }

            // online softmax (rows r0g, r1g per thread; reduce over quad lanes)
            float m0 = -1e30f, m1 = -1e30f;
#pragma unroll
            for (int nt = 0; nt < 8; nt++) {
                m0 = fmaxf(m0, fmaxf(s[nt][0], s[nt][1]));
                m1 = fmaxf(m1, fmaxf(s[nt][2], s[nt][3]));
            }
            m0 = fmaxf(m0, __shfl_xor_sync(0xffffffffu, m0, 1));
            m0 = fmaxf(m0, __shfl_xor_sync(0xffffffffu, m0, 2));
            m1 = fmaxf(m1, __shfl_xor_sync(0xffffffffu, m1, 1));
            m1 = fmaxf(m1, __shfl_xor_sync(0xffffffffu, m1, 2));

            float mn0 = fmaxf(mrun0, m0), mn1 = fmaxf(mrun1, m1);
            float fac0 = __expf(mrun0 - mn0), fac1 = __expf(mrun1 - mn1);
            mrun0 = mn0; mrun1 = mn1;

            float ls0 = 0.f, ls1 = 0.f;
#pragma unroll
            for (int nt = 0; nt < 8; nt++) {
                float p0 = __expf(s[nt][0] - mn0);
                float p1 = __expf(s[nt][1] - mn0);
                float p2 = __expf(s[nt][2] - mn1);
                float p3 = __expf(s[nt][3] - mn1);
                ls0 += p0 + p1;
                ls1 += p2 + p3;
                int c = nt * 8 + 2 * tig;
                *(uint2*)&Ps[(wrow + gid) * FSTR + c]     = make_uint2(f2tf32(p0), f2tf32(p1));
                *(uint2*)&Ps[(wrow + gid + 8) * FSTR + c] = make_uint2(f2tf32(p2), f2tf32(p3));
            }
            ls0 += __shfl_xor_sync(0xffffffffu, ls0, 1);
            ls0 += __shfl_xor_sync(0xffffffffu, ls0, 2);
            ls1 += __shfl_xor_sync(0xffffffffu, ls1, 1);
            ls1 += __shfl_xor_sync(0xffffffffu, ls1, 2);
            lrun0 = lrun0 * fac0 + ls0;
            lrun1 = lrun1 * fac1 + ls1;

#pragma unroll
            for (int nt = 0; nt < 8; nt++) {
                o[nt][0] *= fac0; o[nt][1] *= fac0;
                o[nt][2] *= fac1; o[nt][3] *= fac1;
            }
            __syncwarp();

            // O += P V
#pragma unroll
            for (int ks = 0; ks < 8; ks++) {
                int kk = ks * 8 + tig;
                uint32_t a0 = Ps[(wrow + gid) * FSTR + kk];
                uint32_t a1 = Ps[(wrow + gid + 8) * FSTR + kk];
                uint32_t a2 = Ps[(wrow + gid) * FSTR + kk + 4];
                uint32_t a3 = Ps[(wrow + gid + 8) * FSTR + kk + 4];
#pragma unroll
                for (int nt = 0; nt < 8; nt++) {
                    uint32_t b0 = Vs[(ks * 8 + tig) * FSTR + nt * 8 + gid];
                    uint32_t b1 = Vs[(ks * 8 + tig + 4) * FSTR + nt * 8 + gid];
                    mma_tf32(o[nt], a0, a1, a2, a3, b0, b1);
                }
            }
        }
    }

    // epilogue
    float il0 = 1.0f / lrun0, il1 = 1.0f / lrun1;
    size_t r0 = (size_t)b * SEQ + grow + gid;
    size_t r1 = r0 + 8;
#pragma unroll
    for (int nt = 0; nt < 8; nt++) {
        int col = h * D_HEAD + nt * 8 + 2 * tig;
        *(float2*)(z + r0 * D_MODEL + col) = make_float2(o[nt][0] * il0, o[nt][1] * il0);
        *(float2*)(z + r1 * D_MODEL + col) = make_float2(o[nt][2] * il1, o[nt][3] * il1);
    }
}

// ---------------- launch ----------------
extern "C" void kernel_launch(void* const* d_in, const int* in_sizes, int n_in,
                              void* d_out, int out_size) {
    const float* x  = (const float*)d_in[0];
    const float* Wq = (const float*)d_in[1];
    const float* Wk = (const float*)d_in[2];
    const float* Wv = (const float*)d_in[3];
    const float* Wo = (const float*)d_in[4];   // [h*64+d][m] row-major
    const float* bq = (const float*)d_in[5];
    const float* bk = (const float*)d_in[6];
    const float* bv = (const float*)d_in[7];
    const float* bo = (const float*)d_in[8];
    float* out = (float*)d_out;

    float *wt, *bias, *qkv, *zbuf;
    cudaGetSymbolAddress((void**)&wt,   g_wt);
    cudaGetSymbolAddress((void**)&bias, g_bias);
    cudaGetSymbolAddress((void**)&qkv,  g_qkv);
    cudaGetSymbolAddress((void**)&zbuf, g_z);

    {
        int total = 3 * N_HEADS * D_MODEL * D_HEAD;
        pack_w_kernel<<<(total + 255) / 256, 256>>>(Wq, Wk, Wv);
        pack_bias_kernel<<<(QKV_N + 255) / 256, 256>>>(bq, bk, bv);
    }

    {   // QKV projection
        dim3 grid(QKV_N / TBN, ROWS / TBM);
        tf32_gemm_bias<<<grid, 256>>>(x, wt, qkv, bias, ROWS, QKV_N, D_MODEL);
    }

    {   // flash attention
        int smem = (128 + 64 + 64 + 128) * FSTR * (int)sizeof(uint32_t);  // 104448
        cudaFuncSetAttribute(flash_tf32_kernel,
                             cudaFuncAttributeMaxDynamicSharedMemorySize, smem);
        dim3 grid(SEQ / 128, N_HEADS, BATCH);
        flash_tf32_kernel<<<grid, 256, smem>>>(qkv, zbuf);
    }

    {   // output projection
        dim3 grid(D_MODEL / TBN, ROWS / TBM);
        tf32_gemm_bias<<<grid, 256>>>(zbuf, Wo, out, bo, ROWS, D_MODEL, D_MODEL);
    }
}

// round 4
// speedup vs baseline: 3.0660x; 1.1907x over previous
#include <cuda_runtime.h>
#include <math.h>
#include <stdint.h>

#define N_HEADS 16
#define D_MODEL 1024
#define D_HEAD  64
#define BATCH   2
#define SEQ     2048
#define ROWS    (BATCH*SEQ)          // 4096
#define QKV_N   (3*N_HEADS*D_HEAD)   // 3072

// ---------------- device scratch ----------------
__device__ float g_wt[D_MODEL * QKV_N];     // W_QKV packed [k=m][n], tf32-rounded
__device__ float g_wo[D_MODEL * D_MODEL];   // W_O [k][n], tf32-rounded
__device__ float g_bias[QKV_N];
__device__ float g_xr[(size_t)ROWS * D_MODEL];   // x, tf32-rounded
__device__ float g_qkv[(size_t)ROWS * QKV_N];    // tf32-rounded by GEMM1 epilogue
__device__ float g_z[(size_t)ROWS * D_MODEL];    // tf32-rounded by flash epilogue

// ---------------- helpers ----------------
__device__ __forceinline__ uint32_t f2tf32(float f) {
    uint32_t u;
    asm("cvt.rna.tf32.f32 %0, %1;" : "=r"(u) : "f"(f));
    return u;
}
__device__ __forceinline__ float roundtf(float f) { return __uint_as_float(f2tf32(f)); }

__device__ __forceinline__ void mma_tf32(float* c,
                                         uint32_t a0, uint32_t a1, uint32_t a2, uint32_t a3,
                                         uint32_t b0, uint32_t b1) {
    asm volatile(
        "mma.sync.aligned.m16n8k8.row.col.f32.tf32.tf32.f32 "
        "{%0,%1,%2,%3}, {%4,%5,%6,%7}, {%8,%9}, {%0,%1,%2,%3};"
        : "+f"(c[0]), "+f"(c[1]), "+f"(c[2]), "+f"(c[3])
        : "r"(a0), "r"(a1), "r"(a2), "r"(a3), "r"(b0), "r"(b1));
}

__device__ __forceinline__ uint32_t smem_u32(const void* p) {
    uint32_t a;
    asm("{ .reg .u64 t; cvta.to.shared.u64 t, %1; cvt.u32.u64 %0, t; }" : "=r"(a) : "l"(p));
    return a;
}
__device__ __forceinline__ void cpasync16(uint32_t dst, const void* src) {
    asm volatile("cp.async.cg.shared.global [%0], [%1], 16;" :: "r"(dst), "l"(src));
}
__device__ __forceinline__ void cp_commit() { asm volatile("cp.async.commit_group;"); }

// ---------------- pack kernels (tf32 pre-round) ----------------
__global__ void pack_wt_kernel(const float* __restrict__ Wq,
                               const float* __restrict__ Wk,
                               const float* __restrict__ Wv) {
    int idx = blockIdx.x * 256 + threadIdx.x;   // (which,h,m,d), d fastest
    const int total = 3 * N_HEADS * D_MODEL * D_HEAD;
    if (idx >= total) return;
    int d = idx & 63;
    int m = (idx >> 6) & 1023;
    int h = (idx >> 16) & 15;
    int which = idx >> 20;
    const float* W = (which == 0) ? Wq : (which == 1) ? Wk : Wv;
    float v = W[idx & ((1 << 20) - 1)];
    g_wt[(size_t)m * QKV_N + which * 1024 + h * 64 + d] = roundtf(v);
}

__global__ void round_wo_kernel(const float* __restrict__ Wo) {
    int idx = blockIdx.x * 256 + threadIdx.x;
    if (idx >= D_MODEL * D_MODEL) return;
    g_wo[idx] = roundtf(Wo[idx]);
}

__global__ void pack_bias_kernel(const float* __restrict__ bq,
                                 const float* __restrict__ bk,
                                 const float* __restrict__ bv) {
    int i = blockIdx.x * 256 + threadIdx.x;
    if (i >= QKV_N) return;
    float v;
    if (i < 1024) v = bq[i];
    else if (i < 2048) v = bk[i - 1024];
    else v = bv[i - 2048];
    g_bias[i] = v;
}

__global__ void round_x_kernel(const float* __restrict__ x) {
    int idx = blockIdx.x * 256 + threadIdx.x;
    if (idx >= ROWS * D_MODEL) return;
    g_xr[idx] = roundtf(x[idx]);
}

// ---------------- tf32 mma.sync GEMM with cp.async double-buffer ----------------
// C[M,N] = A[M,K]*B[K,N] + bias.  A,B pre-rounded to tf32.  round_out: round C.
#define TBM 128
#define TBN 128
#define TBK 16
#define AST 20    // A smem stride (floats): [m][k], 16B aligned, conflict-free
#define BST 132   // B smem stride (floats): [k][n]

__global__ __launch_bounds__(256)
void tf32_gemm_ca(const float* __restrict__ A, const float* __restrict__ B,
                  float* __restrict__ C, const float* __restrict__ bias,
                  int M, int N, int K, int round_out) {
    __shared__ uint32_t As[2][TBM][AST];
    __shared__ uint32_t Bs[2][TBK][BST];

    const int tid  = threadIdx.x;
    const int lane = tid & 31;
    const int warp = tid >> 5;
    const int gid  = lane >> 2;
    const int tig  = lane & 3;
    const int wm   = (warp >> 2) * 64;
    const int wn   = (warp & 3) * 32;
    const int br   = blockIdx.y, bc = blockIdx.x;

    const float* Ab = A + (size_t)br * TBM * K;
    const float* Bb = B + (size_t)bc * TBN;

    const uint32_t sa = smem_u32(&As[0][0][0]);
    const uint32_t sbm = smem_u32(&Bs[0][0][0]);

    // A: 512 16B-chunks/tile -> 2 per thread. chunk cid: row=cid>>2, kc=(cid&3)*4
    // B: 512 chunks: row=cid>>5, nc=(cid&31)*4
    auto load_tile = [&](int kt, int buf) {
        const int k0 = kt * TBK;
#pragma unroll
        for (int i = 0; i < 2; i++) {
            int cid = i * 256 + tid;
            int row = cid >> 2, kc = (cid & 3) << 2;
            cpasync16(sa + (uint32_t)(buf * TBM * AST + row * AST + kc) * 4,
                      Ab + (size_t)row * K + k0 + kc);
        }
#pragma unroll
        for (int i = 0; i < 2; i++) {
            int cid = i * 256 + tid;
            int row = cid >> 5, nc = (cid & 31) << 2;
            cpasync16(sbm + (uint32_t)(buf * TBK * BST + row * BST + nc) * 4,
                      Bb + (size_t)(k0 + row) * N + nc);
        }
        cp_commit();
    };

    float acc[4][4][4];
#pragma unroll
    for (int mt = 0; mt < 4; mt++)
#pragma unroll
        for (int nt = 0; nt < 4; nt++)
#pragma unroll
            for (int e = 0; e < 4; e++) acc[mt][nt][e] = 0.f;

    load_tile(0, 0);

    const int NT = K / TBK;
    for (int t = 0; t < NT; t++) {
        const int s = t & 1;
        if (t + 1 < NT) {
            load_tile(t + 1, s ^ 1);
            asm volatile("cp.async.wait_group 1;" ::: "memory");
        } else {
            asm volatile("cp.async.wait_group 0;" ::: "memory");
        }
        __syncthreads();

#pragma unroll
        for (int ks = 0; ks < 2; ks++) {
            const int kk = ks * 8 + tig;
            uint32_t af[4][4], bf[4][2];
#pragma unroll
            for (int mt = 0; mt < 4; mt++) {
                int m0 = wm + mt * 16 + gid;
                af[mt][0] = As[s][m0][kk];
                af[mt][1] = As[s][m0 + 8][kk];
                af[mt][2] = As[s][m0][kk + 4];
                af[mt][3] = As[s][m0 + 8][kk + 4];
            }
#pragma unroll
            for (int nt = 0; nt < 4; nt++) {
                int n0 = wn + nt * 8 + gid;
                bf[nt][0] = Bs[s][kk][n0];
                bf[nt][1] = Bs[s][kk + 4][n0];
            }
#pragma unroll
            for (int mt = 0; mt < 4; mt++)
#pragma unroll
                for (int nt = 0; nt < 4; nt++)
                    mma_tf32(acc[mt][nt], af[mt][0], af[mt][1], af[mt][2], af[mt][3],
                             bf[nt][0], bf[nt][1]);
        }
        __syncthreads();
    }

    // epilogue
#pragma unroll
    for (int mt = 0; mt < 4; mt++) {
        size_t r0 = (size_t)br * TBM + wm + mt * 16 + gid;
        size_t r1 = r0 + 8;
#pragma unroll
        for (int nt = 0; nt < 4; nt++) {
            int col = bc * TBN + wn + nt * 8 + 2 * tig;
            float b0v = bias[col], b1v = bias[col + 1];
            float2 v0, v1;
            if (round_out) {
                v0 = make_float2(roundtf(acc[mt][nt][0] + b0v), roundtf(acc[mt][nt][1] + b1v));
                v1 = make_float2(roundtf(acc[mt][nt][2] + b0v), roundtf(acc[mt][nt][3] + b1v));
            } else {
                v0 = make_float2(acc[mt][nt][0] + b0v, acc[mt][nt][1] + b1v);
                v1 = make_float2(acc[mt][nt][2] + b0v, acc[mt][nt][3] + b1v);
            }
            *(float2*)(C + r0 * N + col) = v0;
            *(float2*)(C + r1 * N + col) = v1;
        }
    }
}

// ---------------- flash attention: tf32 mma.sync + cp.async double-buffered K/V ----
#define FSTR 68   // floats; 272B row stride (16B-aligned)

__global__ __launch_bounds__(256)
void flash_tf32_kernel(const float* __restrict__ qkv, float* __restrict__ z) {
    extern __shared__ uint32_t sm[];
    uint32_t* Qs = sm;                      // [128][FSTR]
    uint32_t* Ks = Qs + 128 * FSTR;         // [2][64][FSTR]
    uint32_t* Vs = Ks + 2 * 64 * FSTR;      // [2][64][FSTR]
    uint32_t* Ps = Vs + 2 * 64 * FSTR;      // [128][FSTR]

    const int tid  = threadIdx.x;
    const int lane = tid & 31;
    const int warp = tid >> 5;
    const int gid  = lane >> 2;
    const int tig  = lane & 3;
    const int qb = gridDim.x - 1 - blockIdx.x;   // heavy blocks first
    const int h = blockIdx.y, b = blockIdx.z;

    const float* base = qkv + (size_t)b * SEQ * QKV_N + h * D_HEAD;
    const float* qptr = base + (size_t)qb * 128 * QKV_N;

    const uint32_t sQ = smem_u32(Qs);
    const uint32_t sK = smem_u32(Ks);
    const uint32_t sV = smem_u32(Vs);

    // K/V tile loader: 64 rows x 16 chunks each => 4+4 cp.async per thread
    auto load_kv = [&](int jb, int buf) {
        const float* kp = base + (size_t)jb * 64 * QKV_N + 1024;
        const float* vp = kp + 1024;
        const uint32_t off = (uint32_t)(buf * 64 * FSTR) * 4;
#pragma unroll
        for (int i = 0; i < 4; i++) {
            int cid = i * 256 + tid;            // 0..1023
            int r = cid >> 4, c = (cid & 15) << 2;
            uint32_t doff = (uint32_t)(r * FSTR + c) * 4;
            cpasync16(sK + off + doff, kp + (size_t)r * QKV_N + c);
            cpasync16(sV + off + doff, vp + (size_t)r * QKV_N + c);
        }
        cp_commit();
    };

    // Q: 128 rows x 16 chunks = 2048 -> 8 per thread (raw, unscaled)
    {
#pragma unroll
        for (int i = 0; i < 8; i++) {
            int cid = i * 256 + tid;
            int r = cid >> 4, c = (cid & 15) << 2;
            cpasync16(sQ + (uint32_t)(r * FSTR + c) * 4, qptr + (size_t)r * QKV_N + c);
        }
        load_kv(0, 0);   // Q + KV0 share group 0
    }

    float o[8][4];
#pragma unroll
    for (int nt = 0; nt < 8; nt++)
#pragma unroll
        for (int e = 0; e < 4; e++) o[nt][e] = 0.f;
    float mrun0 = -1e30f, mrun1 = -1e30f, lrun0 = 0.f, lrun1 = 0.f;

    const int wrow = warp * 16;
    const int grow = qb * 128 + wrow;
    const int jbmax = (qb * 128 + 127) / 64;

    for (int jb = 0; jb <= jbmax; jb++) {
        const int s = jb & 1;
        if (jb + 1 <= jbmax) {
            load_kv(jb + 1, s ^ 1);
            asm volatile("cp.async.wait_group 1;" ::: "memory");
        } else {
            asm volatile("cp.async.wait_group 0;" ::: "memory");
        }
        __syncthreads();

        const uint32_t* Kb = Ks + s * 64 * FSTR;
        const uint32_t* Vb = Vs + s * 64 * FSTR;

        bool active = (jb * 64 <= grow + 15);
        if (active) {
            float sc[8][4];
#pragma unroll
            for (int nt = 0; nt < 8; nt++)
#pragma unroll
                for (int e = 0; e < 4; e++) sc[nt][e] = 0.f;

#pragma unroll
            for (int ks = 0; ks < 8; ks++) {
                int kk = ks * 8 + tig;
                uint32_t a0 = Qs[(wrow + gid) * FSTR + kk];
                uint32_t a1 = Qs[(wrow + gid + 8) * FSTR + kk];
                uint32_t a2 = Qs[(wrow + gid) * FSTR + kk + 4];
                uint32_t a3 = Qs[(wrow + gid + 8) * FSTR + kk + 4];
#pragma unroll
                for (int nt = 0; nt < 8; nt++) {
                    uint32_t b0 = Kb[(nt * 8 + gid) * FSTR + kk];
                    uint32_t b1 = Kb[(nt * 8 + gid) * FSTR + kk + 4];
                    mma_tf32(sc[nt], a0, a1, a2, a3, b0, b1);
                }
            }

            // scale by 1/sqrt(64) (power of two, exact)
#pragma unroll
            for (int nt = 0; nt < 8; nt++)
#pragma unroll
                for (int e = 0; e < 4; e++) sc[nt][e] *= 0.125f;

            int r0g = grow + gid, r1g = r0g + 8;
            if (jb * 64 + 63 > grow) {
#pragma unroll
                for (int nt = 0; nt < 8; nt++) {
                    int col = jb * 64 + nt * 8 + 2 * tig;
                    if (col     > r0g) sc[nt][0] = -1e30f;
                    if (col + 1 > r0g) sc[nt][1] = -1e30f;
                    if (col     > r1g) sc[nt][2] = -1e30f;
                    if (col + 1 > r1g) sc[nt][3] = -1e30f;
                }
            }

            float m0 = -1e30f, m1 = -1e30f;
#pragma unroll
            for (int nt = 0; nt < 8; nt++) {
                m0 = fmaxf(m0, fmaxf(sc[nt][0], sc[nt][1]));
                m1 = fmaxf(m1, fmaxf(sc[nt][2], sc[nt][3]));
            }
            m0 = fmaxf(m0, __shfl_xor_sync(0xffffffffu, m0, 1));
            m0 = fmaxf(m0, __shfl_xor_sync(0xffffffffu, m0, 2));
            m1 = fmaxf(m1, __shfl_xor_sync(0xffffffffu, m1, 1));
            m1 = fmaxf(m1, __shfl_xor_sync(0xffffffffu, m1, 2));

            float mn0 = fmaxf(mrun0, m0), mn1 = fmaxf(mrun1, m1);
            float fac0 = __expf(mrun0 - mn0), fac1 = __expf(mrun1 - mn1);
            mrun0 = mn0; mrun1 = mn1;

            float ls0 = 0.f, ls1 = 0.f;
#pragma unroll
            for (int nt = 0; nt < 8; nt++) {
                float p0 = __expf(sc[nt][0] - mn0);
                float p1 = __expf(sc[nt][1] - mn0);
                float p2 = __expf(sc[nt][2] - mn1);
                float p3 = __expf(sc[nt][3] - mn1);
                ls0 += p0 + p1;
                ls1 += p2 + p3;
                int c = nt * 8 + 2 * tig;
                *(uint2*)&Ps[(wrow + gid) * FSTR + c]     = make_uint2(f2tf32(p0), f2tf32(p1));
                *(uint2*)&Ps[(wrow + gid + 8) * FSTR + c] = make_uint2(f2tf32(p2), f2tf32(p3));
            }
            ls0 += __shfl_xor_sync(0xffffffffu, ls0, 1);
            ls0 += __shfl_xor_sync(0xffffffffu, ls0, 2);
            ls1 += __shfl_xor_sync(0xffffffffu, ls1, 1);
            ls1 += __shfl_xor_sync(0xffffffffu, ls1, 2);
            lrun0 = lrun0 * fac0 + ls0;
            lrun1 = lrun1 * fac1 + ls1;

#pragma unroll
            for (int nt = 0; nt < 8; nt++) {
                o[nt][0] *= fac0; o[nt][1] *= fac0;
                o[nt][2] *= fac1; o[nt][3] *= fac1;
            }
            __syncwarp();

#pragma unroll
            for (int ks = 0; ks < 8; ks++) {
                int kk = ks * 8 + tig;
                uint32_t a0 = Ps[(wrow + gid) * FSTR + kk];
                uint32_t a1 = Ps[(wrow + gid + 8) * FSTR + kk];
                uint32_t a2 = Ps[(wrow + gid) * FSTR + kk + 4];
                uint32_t a3 = Ps[(wrow + gid + 8) * FSTR + kk + 4];
#pragma unroll
                for (int nt = 0; nt < 8; nt++) {
                    uint32_t b0 = Vb[(ks * 8 + tig) * FSTR + nt * 8 + gid];
                    uint32_t b1 = Vb[(ks * 8 + tig + 4) * FSTR + nt * 8 + gid];
                    mma_tf32(o[nt], a0, a1, a2, a3, b0, b1);
                }
            }
        }
        __syncthreads();
    }

    // epilogue: tf32-rounded z (GEMM2 consumes raw)
    float il0 = 1.0f / lrun0, il1 = 1.0f / lrun1;
    size_t r0 = (size_t)b * SEQ + grow + gid;
    size_t r1 = r0 + 8;
#pragma unroll
    for (int nt = 0; nt < 8; nt++) {
        int col = h * D_HEAD + nt * 8 + 2 * tig;
        *(float2*)(z + r0 * D_MODEL + col) =
            make_float2(roundtf(o[nt][0] * il0), roundtf(o[nt][1] * il0));
        *(float2*)(z + r1 * D_MODEL + col) =
            make_float2(roundtf(o[nt][2] * il1), roundtf(o[nt][3] * il1));
    }
}

// ---------------- launch ----------------
extern "C" void kernel_launch(void* const* d_in, const int* in_sizes, int n_in,
                              void* d_out, int out_size) {
    const float* x  = (const float*)d_in[0];
    const float* Wq = (const float*)d_in[1];
    const float* Wk = (const float*)d_in[2];
    const float* Wv = (const float*)d_in[3];
    const float* Wo = (const float*)d_in[4];
    const float* bq = (const float*)d_in[5];
    const float* bk = (const float*)d_in[6];
    const float* bv = (const float*)d_in[7];
    const float* bo = (const float*)d_in[8];
    float* out = (float*)d_out;

    float *wt, *wo, *bias, *xr, *qkv, *zbuf;
    cudaGetSymbolAddress((void**)&wt,   g_wt);
    cudaGetSymbolAddress((void**)&wo,   g_wo);
    cudaGetSymbolAddress((void**)&bias, g_bias);
    cudaGetSymbolAddress((void**)&xr,   g_xr);
    cudaGetSymbolAddress((void**)&qkv,  g_qkv);
    cudaGetSymbolAddress((void**)&zbuf, g_z);

    pack_wt_kernel<<<(3 * N_HEADS * D_MODEL * D_HEAD + 255) / 256, 256>>>(Wq, Wk, Wv);
    round_wo_kernel<<<(D_MODEL * D_MODEL + 255) / 256, 256>>>(Wo);
    pack_bias_kernel<<<(QKV_N + 255) / 256, 256>>>(bq, bk, bv);
    round_x_kernel<<<(ROWS * D_MODEL + 255) / 256, 256>>>(x);

    {   // QKV projection (rounded output)
        dim3 grid(QKV_N / TBN, ROWS / TBM);
        tf32_gemm_ca<<<grid, 256>>>(xr, wt, qkv, bias, ROWS, QKV_N, D_MODEL, 1);
    }

    {   // flash attention
        int smem = (128 + 128 + 128 + 128) * FSTR * (int)sizeof(uint32_t);  // 139264
        cudaFuncSetAttribute(flash_tf32_kernel,
                             cudaFuncAttributeMaxDynamicSharedMemorySize, smem);
        dim3 grid(SEQ / 128, N_HEADS, BATCH);
        flash_tf32_kernel<<<grid, 256, smem>>>(qkv, zbuf);
    }

    {   // output projection (raw fp32 output)
        dim3 grid(D_MODEL / TBN, ROWS / TBM);
        tf32_gemm_ca<<<grid, 256>>>(zbuf, wo, out, bo, ROWS, D_MODEL, D_MODEL, 0);
    }
}

// round 5
// speedup vs baseline: 6.6113x; 2.1563x over previous
#include <cuda_runtime.h>
#include <cuda_fp16.h>
#include <math.h>
#include <stdint.h>

#define N_HEADS 16
#define D_MODEL 1024
#define D_HEAD  64
#define BATCH   2
#define SEQ     2048
#define ROWS    (BATCH*SEQ)          // 4096
#define QKV_N   (3*N_HEADS*D_HEAD)   // 3072

// ---------------- device scratch ----------------
__device__ __half g_wt[QKV_N * D_MODEL];     // W_QKV^T  [n][k]
__device__ __half g_wo[D_MODEL * D_MODEL];   // W_O^T    [n][k]
__device__ float  g_bias[QKV_N];
__device__ __half g_xh[(size_t)ROWS * D_MODEL];
__device__ __half g_qkv[(size_t)ROWS * QKV_N];
__device__ __half g_zh[(size_t)ROWS * D_MODEL];

// ---------------- helpers ----------------
__device__ __forceinline__ uint32_t packh2(float lo, float hi) {
    __half2 h = __floats2half2_rn(lo, hi);
    return *(uint32_t*)&h;
}

__device__ __forceinline__ void mma_f16(float* c,
                                        uint32_t a0, uint32_t a1, uint32_t a2, uint32_t a3,
                                        uint32_t b0, uint32_t b1) {
    asm volatile(
        "mma.sync.aligned.m16n8k16.row.col.f32.f16.f16.f32 "
        "{%0,%1,%2,%3}, {%4,%5,%6,%7}, {%8,%9}, {%0,%1,%2,%3};"
        : "+f"(c[0]), "+f"(c[1]), "+f"(c[2]), "+f"(c[3])
        : "r"(a0), "r"(a1), "r"(a2), "r"(a3), "r"(b0), "r"(b1));
}

__device__ __forceinline__ uint32_t smem_u32(const void* p) {
    uint32_t a;
    asm("{ .reg .u64 t; cvta.to.shared.u64 t, %1; cvt.u32.u64 %0, t; }" : "=r"(a) : "l"(p));
    return a;
}
__device__ __forceinline__ void cpasync16(uint32_t dst, const void* src) {
    asm volatile("cp.async.cg.shared.global [%0], [%1], 16;" :: "r"(dst), "l"(src));
}
__device__ __forceinline__ void cp_commit() { asm volatile("cp.async.commit_group;"); }

// ---------------- pack kernels ----------------
// W_QKV: [h][m][d] fp32  ->  g_wt [n = which*1024 + h*64 + d][m] half (tiled transpose)
__global__ __launch_bounds__(256)
void pack_wqkv_kernel(const float* __restrict__ Wq, const float* __restrict__ Wk,
                      const float* __restrict__ Wv) {
    __shared__ float sm[32][33];
    const int tx = threadIdx.x, ty = threadIdx.y;     // (32, 8)
    const int mt = blockIdx.x, dt = blockIdx.y;       // m-tile(32), d-tile(2)
    const int wh = blockIdx.z;                        // which*16 + h
    const int which = wh >> 4, h = wh & 15;
    const float* W = (which == 0) ? Wq : (which == 1) ? Wk : Wv;
    const float* base = W + h * (D_MODEL * D_HEAD);
#pragma unroll
    for (int i = 0; i < 4; i++) {
        int m = mt * 32 + ty + i * 8;
        sm[ty + i * 8][tx] = base[m * 64 + dt * 32 + tx];   // sm[m_local][d_local]
    }
    __syncthreads();
#pragma unroll
    for (int i = 0; i < 4; i++) {
        int dl = ty + i * 8;
        int n = which * 1024 + h * 64 + dt * 32 + dl;
        g_wt[(size_t)n * D_MODEL + mt * 32 + tx] = __float2half_rn(sm[tx][dl]);
    }
}

// W_O [k][n] fp32 -> g_wo [n][k] half
__global__ __launch_bounds__(256)
void pack_wo_kernel(const float* __restrict__ Wo) {
    __shared__ float sm[32][33];
    const int tx = threadIdx.x, ty = threadIdx.y;
    const int kt = blockIdx.x, nt = blockIdx.y;
#pragma unroll
    for (int i = 0; i < 4; i++) {
        int k = kt * 32 + ty + i * 8;
        sm[ty + i * 8][tx] = Wo[(size_t)k * 1024 + nt * 32 + tx];
    }
    __syncthreads();
#pragma unroll
    for (int i = 0; i < 4; i++) {
        int nl = ty + i * 8;
        g_wo[(size_t)(nt * 32 + nl) * 1024 + kt * 32 + tx] = __float2half_rn(sm[tx][nl]);
    }
}

__global__ void pack_bias_kernel(const float* __restrict__ bq,
                                 const float* __restrict__ bk,
                                 const float* __restrict__ bv) {
    int i = blockIdx.x * 256 + threadIdx.x;
    if (i >= QKV_N) return;
    float v;
    if (i < 1024) v = bq[i];
    else if (i < 2048) v = bk[i - 1024];
    else v = bv[i - 2048];
    g_bias[i] = v;
}

__global__ void x_to_half_kernel(const float* __restrict__ x) {
    int idx = blockIdx.x * 256 + threadIdx.x;      // processes 4 elems
    const float4 v = *(const float4*)(x + (size_t)idx * 4);
    uint2 o;
    o.x = packh2(v.x, v.y);
    o.y = packh2(v.z, v.w);
    *(uint2*)(g_xh + (size_t)idx * 4) = o;
}

// ---------------- fp16 mma GEMM: C[M,N] = A[M,K] * Bt[N,K]^T + bias ----------------
// smem: SW128-swizzled 128B rows (64 halfs). TBM=TBN=128, TBK=64.
#define GA(buf) ((buf) * 16384)
#define GB(buf) (32768 + (buf) * 16384)
#define G_SMEM  65536

__global__ __launch_bounds__(256)
void h16_gemm(const __half* __restrict__ A, const __half* __restrict__ Bt,
              void* __restrict__ Cout, const float* __restrict__ bias,
              int M, int N, int K, int out_half) {
    extern __shared__ char smg[];
    const uint32_t sb = smem_u32(smg);
    const int tid  = threadIdx.x;
    const int lane = tid & 31;
    const int warp = tid >> 5;
    const int gid  = lane >> 2;
    const int tig  = lane & 3;
    const int wm   = (warp >> 2) * 64;    // 0 / 64
    const int wn   = (warp & 3) * 32;     // 0..96
    const int br   = blockIdx.y, bc = blockIdx.x;

    const __half* Ab = A  + (size_t)br * 128 * K;
    const __half* Bb = Bt + (size_t)bc * 128 * K;

    // loader: 128 rows x 8 x 16B chunks = 1024 chunks each for A and B -> 4/thread
    auto load_tile = [&](int kt, int buf) {
        const int k0 = kt * 64;
#pragma unroll
        for (int i = 0; i < 4; i++) {
            int c = i * 256 + tid;
            int row = c >> 3, ch = c & 7;
            uint32_t d = row * 128 + ((ch * 16) ^ ((row & 7) << 4));
            cpasync16(sb + GA(buf) + d, Ab + (size_t)row * K + k0 + ch * 8);
        }
#pragma unroll
        for (int i = 0; i < 4; i++) {
            int c = i * 256 + tid;
            int row = c >> 3, ch = c & 7;
            uint32_t d = row * 128 + ((ch * 16) ^ ((row & 7) << 4));
            cpasync16(sb + GB(buf) + d, Bb + (size_t)row * K + k0 + ch * 8);
        }
        cp_commit();
    };

    float acc[4][4][4];
#pragma unroll
    for (int mt = 0; mt < 4; mt++)
#pragma unroll
        for (int nt = 0; nt < 4; nt++)
#pragma unroll
            for (int e = 0; e < 4; e++) acc[mt][nt][e] = 0.f;

    load_tile(0, 0);

    const int NT = K / 64;
    for (int t = 0; t < NT; t++) {
        const int s = t & 1;
        if (t + 1 < NT) {
            load_tile(t + 1, s ^ 1);
            asm volatile("cp.async.wait_group 1;" ::: "memory");
        } else {
            asm volatile("cp.async.wait_group 0;" ::: "memory");
        }
        __syncthreads();

        const uint32_t aB = sb + GA(s);
        const uint32_t bB = sb + GB(s);

#pragma unroll
        for (int ks = 0; ks < 4; ks++) {
            const uint32_t c0 = (uint32_t)((ks * 32)      ^ (gid << 4)) + tig * 4;
            const uint32_t c1 = (uint32_t)((ks * 32 + 16) ^ (gid << 4)) + tig * 4;
            uint32_t af[4][4], bf[4][2];
#pragma unroll
            for (int mt = 0; mt < 4; mt++) {
                uint32_t r0 = aB + (wm + mt * 16 + gid) * 128;
                asm("ld.shared.u32 %0, [%1];" : "=r"(af[mt][0]) : "r"(r0 + c0));
                asm("ld.shared.u32 %0, [%1];" : "=r"(af[mt][1]) : "r"(r0 + 1024 + c0));
                asm("ld.shared.u32 %0, [%1];" : "=r"(af[mt][2]) : "r"(r0 + c1));
                asm("ld.shared.u32 %0, [%1];" : "=r"(af[mt][3]) : "r"(r0 + 1024 + c1));
            }
#pragma unroll
            for (int nt = 0; nt < 4; nt++) {
                uint32_t r0 = bB + (wn + nt * 8 + gid) * 128;
                asm("ld.shared.u32 %0, [%1];" : "=r"(bf[nt][0]) : "r"(r0 + c0));
                asm("ld.shared.u32 %0, [%1];" : "=r"(bf[nt][1]) : "r"(r0 + c1));
            }
#pragma unroll
            for (int mt = 0; mt < 4; mt++)
#pragma unroll
                for (int nt = 0; nt < 4; nt++)
                    mma_f16(acc[mt][nt], af[mt][0], af[mt][1], af[mt][2], af[mt][3],
                            bf[nt][0], bf[nt][1]);
        }
        __syncthreads();
    }

    // epilogue
#pragma unroll
    for (int mt = 0; mt < 4; mt++) {
        size_t r0 = (size_t)br * 128 + wm + mt * 16 + gid;
        size_t r1 = r0 + 8;
#pragma unroll
        for (int nt = 0; nt < 4; nt++) {
            int col = bc * 128 + wn + nt * 8 + 2 * tig;
            float b0v = bias[col], b1v = bias[col + 1];
            float v00 = acc[mt][nt][0] + b0v, v01 = acc[mt][nt][1] + b1v;
            float v10 = acc[mt][nt][2] + b0v, v11 = acc[mt][nt][3] + b1v;
            if (out_half) {
                __half* C = (__half*)Cout;
                *(uint32_t*)(C + r0 * N + col) = packh2(v00, v01);
                *(uint32_t*)(C + r1 * N + col) = packh2(v10, v11);
            } else {
                float* C = (float*)Cout;
                *(float2*)(C + r0 * N + col) = make_float2(v00, v01);
                *(float2*)(C + r1 * N + col) = make_float2(v10, v11);
            }
        }
    }
}

// ---------------- fp16 flash attention (causal) ----------------
// smem: Q [128][64]h @0 (16KB), K [2][64][64]h @16384, V [2][64][64]h @32768. 48KB.
#define FQ    0
#define FK(s) (16384 + (s) * 8192)
#define FV(s) (32768 + (s) * 8192)
#define F_SMEM 49152

__global__ __launch_bounds__(256)
void flash_h16_kernel(const __half* __restrict__ qkv, __half* __restrict__ z) {
    extern __shared__ char smf[];
    const uint32_t sb = smem_u32(smf);

    const int tid  = threadIdx.x;
    const int lane = tid & 31;
    const int warp = tid >> 5;
    const int gid  = lane >> 2;
    const int tig  = lane & 3;
    const int qb = gridDim.x - 1 - blockIdx.x;     // heavy blocks first
    const int h = blockIdx.y, b = blockIdx.z;

    const __half* base = qkv + (size_t)b * SEQ * QKV_N + h * D_HEAD;
    const __half* qptr = base + (size_t)qb * 128 * QKV_N;

    auto load_kv = [&](int jb, int buf) {
        const __half* kp = base + (size_t)jb * 64 * QKV_N + 1024;
        const __half* vp = kp + 1024;
#pragma unroll
        for (int i = 0; i < 2; i++) {
            int c = i * 256 + tid;                 // 0..511
            int r = c >> 3, ch = c & 7;
            uint32_t d = r * 128 + ((ch * 16) ^ ((r & 7) << 4));
            cpasync16(sb + FK(buf) + d, kp + (size_t)r * QKV_N + ch * 8);
            cpasync16(sb + FV(buf) + d, vp + (size_t)r * QKV_N + ch * 8);
        }
        cp_commit();
    };

    {   // Q (raw) + KV0 in one group
#pragma unroll
        for (int i = 0; i < 4; i++) {
            int c = i * 256 + tid;                 // 0..1023
            int r = c >> 3, ch = c & 7;
            uint32_t d = r * 128 + ((ch * 16) ^ ((r & 7) << 4));
            cpasync16(sb + FQ + d, qptr + (size_t)r * QKV_N + ch * 8);
        }
        load_kv(0, 0);
    }

    float o[8][4];
#pragma unroll
    for (int nt = 0; nt < 8; nt++)
#pragma unroll
        for (int e = 0; e < 4; e++) o[nt][e] = 0.f;
    float mrun0 = -1e30f, mrun1 = -1e30f, lrun0 = 0.f, lrun1 = 0.f;

    const int wrow = warp * 16;
    const int grow = qb * 128 + wrow;
    const int jbmax = 2 * qb + 1;

    const uint32_t x0 = (uint32_t)(2 * tig) << 4;        // V swizzle consts
    const uint32_t x1 = (uint32_t)(2 * tig + 1) << 4;

    for (int jb = 0; jb <= jbmax; jb++) {
        const int s = jb & 1;
        if (jb + 1 <= jbmax) {
            load_kv(jb + 1, s ^ 1);
            asm volatile("cp.async.wait_group 1;" ::: "memory");
        } else {
            asm volatile("cp.async.wait_group 0;" ::: "memory");
        }
        __syncthreads();

        if (jb * 64 <= grow + 15) {
            const uint32_t qB = sb + FQ;
            const uint32_t kB = sb + FK(s);
            const uint32_t vB = sb + FV(s);

            float sc[8][4];
#pragma unroll
            for (int nt = 0; nt < 8; nt++)
#pragma unroll
                for (int e = 0; e < 4; e++) sc[nt][e] = 0.f;

            // S = Q K^T (4 ksteps of 16 over d=64)
#pragma unroll
            for (int ks = 0; ks < 4; ks++) {
                const uint32_t c0 = (uint32_t)((ks * 32)      ^ (gid << 4)) + tig * 4;
                const uint32_t c1 = (uint32_t)((ks * 32 + 16) ^ (gid << 4)) + tig * 4;
                uint32_t a0, a1, a2, a3;
                uint32_t qr = qB + (wrow + gid) * 128;
                asm("ld.shared.u32 %0, [%1];" : "=r"(a0) : "r"(qr + c0));
                asm("ld.shared.u32 %0, [%1];" : "=r"(a1) : "r"(qr + 1024 + c0));
                asm("ld.shared.u32 %0, [%1];" : "=r"(a2) : "r"(qr + c1));
                asm("ld.shared.u32 %0, [%1];" : "=r"(a3) : "r"(qr + 1024 + c1));
#pragma unroll
                for (int nt = 0; nt < 8; nt++) {
                    uint32_t kr = kB + (nt * 8 + gid) * 128;
                    uint32_t b0, b1;
                    asm("ld.shared.u32 %0, [%1];" : "=r"(b0) : "r"(kr + c0));
                    asm("ld.shared.u32 %0, [%1];" : "=r"(b1) : "r"(kr + c1));
                    mma_f16(sc[nt], a0, a1, a2, a3, b0, b1);
                }
            }

#pragma unroll
            for (int nt = 0; nt < 8; nt++)
#pragma unroll
                for (int e = 0; e < 4; e++) sc[nt][e] *= 0.125f;

            // causal mask
            const int r0g = grow + gid, r1g = r0g + 8;
            if (jb * 64 + 63 > grow) {
#pragma unroll
                for (int nt = 0; nt < 8; nt++) {
                    int col = jb * 64 + nt * 8 + 2 * tig;
                    if (col     > r0g) sc[nt][0] = -1e30f;
                    if (col + 1 > r0g) sc[nt][1] = -1e30f;
                    if (col     > r1g) sc[nt][2] = -1e30f;
                    if (col + 1 > r1g) sc[nt][3] = -1e30f;
                }
            }

            // online softmax
            float m0 = -1e30f, m1 = -1e30f;
#pragma unroll
            for (int nt = 0; nt < 8; nt++) {
                m0 = fmaxf(m0, fmaxf(sc[nt][0], sc[nt][1]));
                m1 = fmaxf(m1, fmaxf(sc[nt][2], sc[nt][3]));
            }
            m0 = fmaxf(m0, __shfl_xor_sync(0xffffffffu, m0, 1));
            m0 = fmaxf(m0, __shfl_xor_sync(0xffffffffu, m0, 2));
            m1 = fmaxf(m1, __shfl_xor_sync(0xffffffffu, m1, 1));
            m1 = fmaxf(m1, __shfl_xor_sync(0xffffffffu, m1, 2));

            float mn0 = fmaxf(mrun0, m0), mn1 = fmaxf(mrun1, m1);
            float fac0 = __expf(mrun0 - mn0), fac1 = __expf(mrun1 - mn1);
            mrun0 = mn0; mrun1 = mn1;

            float ls0 = 0.f, ls1 = 0.f;
#pragma unroll
            for (int nt = 0; nt < 8; nt++) {
                sc[nt][0] = __expf(sc[nt][0] - mn0);
                sc[nt][1] = __expf(sc[nt][1] - mn0);
                sc[nt][2] = __expf(sc[nt][2] - mn1);
                sc[nt][3] = __expf(sc[nt][3] - mn1);
                ls0 += sc[nt][0] + sc[nt][1];
                ls1 += sc[nt][2] + sc[nt][3];
            }
            ls0 += __shfl_xor_sync(0xffffffffu, ls0, 1);
            ls0 += __shfl_xor_sync(0xffffffffu, ls0, 2);
            ls1 += __shfl_xor_sync(0xffffffffu, ls1, 1);
            ls1 += __shfl_xor_sync(0xffffffffu, ls1, 2);
            lrun0 = lrun0 * fac0 + ls0;
            lrun1 = lrun1 * fac1 + ls1;

#pragma unroll
            for (int nt = 0; nt < 8; nt++) {
                o[nt][0] *= fac0; o[nt][1] *= fac0;
                o[nt][2] *= fac1; o[nt][3] *= fac1;
            }

            // O += P V  (P = C-fragment reused as A-fragment, no smem)
#pragma unroll
            for (int ks = 0; ks < 4; ks++) {
                uint32_t a0 = packh2(sc[2 * ks][0],     sc[2 * ks][1]);
                uint32_t a1 = packh2(sc[2 * ks][2],     sc[2 * ks][3]);
                uint32_t a2 = packh2(sc[2 * ks + 1][0], sc[2 * ks + 1][1]);
                uint32_t a3 = packh2(sc[2 * ks + 1][2], sc[2 * ks + 1][3]);
                const uint32_t rlo = vB + (ks * 16 + 2 * tig) * 128 + gid * 2;
#pragma unroll
                for (int nt = 0; nt < 8; nt++) {
                    const uint32_t cc = (uint32_t)nt * 16;
                    uint32_t l0, h0, l1, h1;
                    asm("ld.shared.u16 %0, [%1];" : "=r"(l0) : "r"(rlo + (cc ^ x0)));
                    asm("ld.shared.u16 %0, [%1];" : "=r"(h0) : "r"(rlo + 128 + (cc ^ x1)));
                    asm("ld.shared.u16 %0, [%1];" : "=r"(l1) : "r"(rlo + 1024 + (cc ^ x0)));
                    asm("ld.shared.u16 %0, [%1];" : "=r"(h1) : "r"(rlo + 1152 + (cc ^ x1)));
                    mma_f16(o[nt], a0, a1, a2, a3, l0 | (h0 << 16), l1 | (h1 << 16));
                }
            }
        }
        __syncthreads();
    }

    // epilogue: z half
    float il0 = 1.0f / lrun0, il1 = 1.0f / lrun1;
    size_t r0 = (size_t)b * SEQ + grow + gid;
    size_t r1 = r0 + 8;
#pragma unroll
    for (int nt = 0; nt < 8; nt++) {
        int col = h * D_HEAD + nt * 8 + 2 * tig;
        *(uint32_t*)(z + r0 * D_MODEL + col) = packh2(o[nt][0] * il0, o[nt][1] * il0);
        *(uint32_t*)(z + r1 * D_MODEL + col) = packh2(o[nt][2] * il1, o[nt][3] * il1);
    }
}

// ---------------- launch ----------------
extern "C" void kernel_launch(void* const* d_in, const int* in_sizes, int n_in,
                              void* d_out, int out_size) {
    const float* x  = (const float*)d_in[0];
    const float* Wq = (const float*)d_in[1];
    const float* Wk = (const float*)d_in[2];
    const float* Wv = (const float*)d_in[3];
    const float* Wo = (const float*)d_in[4];
    const float* bq = (const float*)d_in[5];
    const float* bk = (const float*)d_in[6];
    const float* bv = (const float*)d_in[7];
    const float* bo = (const float*)d_in[8];
    float* out = (float*)d_out;

    __half *wt, *wo, *xh, *qkv, *zh;
    float *bias;
    cudaGetSymbolAddress((void**)&wt,   g_wt);
    cudaGetSymbolAddress((void**)&wo,   g_wo);
    cudaGetSymbolAddress((void**)&bias, g_bias);
    cudaGetSymbolAddress((void**)&xh,   g_xh);
    cudaGetSymbolAddress((void**)&qkv,  g_qkv);
    cudaGetSymbolAddress((void**)&zh,   g_zh);

    {   // packs
        dim3 blk(32, 8);
        pack_wqkv_kernel<<<dim3(32, 2, 48), blk>>>(Wq, Wk, Wv);
        pack_wo_kernel<<<dim3(32, 32), blk>>>(Wo);
        pack_bias_kernel<<<(QKV_N + 255) / 256, 256>>>(bq, bk, bv);
        x_to_half_kernel<<<(ROWS * D_MODEL / 4 + 255) / 256, 256>>>(x);
    }

    cudaFuncSetAttribute(h16_gemm, cudaFuncAttributeMaxDynamicSharedMemorySize, G_SMEM);
    cudaFuncSetAttribute(flash_h16_kernel, cudaFuncAttributeMaxDynamicSharedMemorySize, F_SMEM);

    {   // QKV projection -> half qkv
        dim3 grid(QKV_N / 128, ROWS / 128);
        h16_gemm<<<grid, 256, G_SMEM>>>(xh, wt, qkv, bias, ROWS, QKV_N, D_MODEL, 1);
    }

    {   // flash attention -> half z
        dim3 grid(SEQ / 128, N_HEADS, BATCH);
        flash_h16_kernel<<<grid, 256, F_SMEM>>>(qkv, zh);
    }

    {   // output projection -> fp32 out
        dim3 grid(D_MODEL / 128, ROWS / 128);
        h16_gemm<<<grid, 256, G_SMEM>>>(zh, wo, out, bo, ROWS, D_MODEL, D_MODEL, 0);
    }
}

// round 7
// speedup vs baseline: 7.9413x; 1.2012x over previous
#include <cuda_runtime.h>
#include <cuda_fp16.h>
#include <math.h>
#include <stdint.h>

#define N_HEADS 16
#define D_MODEL 1024
#define D_HEAD  64
#define BATCH   2
#define SEQ     2048
#define ROWS    (BATCH*SEQ)          // 4096
#define QKV_N   (3*N_HEADS*D_HEAD)   // 3072

// ---------------- device scratch ----------------
__device__ __half g_wt[QKV_N * D_MODEL];     // W_QKV^T  [n][k]
__device__ __half g_wo[D_MODEL * D_MODEL];   // W_O^T    [n][k]
__device__ float  g_bias[QKV_N];
__device__ __half g_xh[(size_t)ROWS * D_MODEL];
__device__ __half g_qkv[(size_t)ROWS * QKV_N];
__device__ __half g_zh[(size_t)ROWS * D_MODEL];

// ---------------- helpers ----------------
__device__ __forceinline__ uint32_t packh2(float lo, float hi) {
    __half2 h = __floats2half2_rn(lo, hi);
    return *(uint32_t*)&h;
}

__device__ __forceinline__ void mma_f16(float* c,
                                        uint32_t a0, uint32_t a1, uint32_t a2, uint32_t a3,
                                        uint32_t b0, uint32_t b1) {
    asm volatile(
        "mma.sync.aligned.m16n8k16.row.col.f32.f16.f16.f32 "
        "{%0,%1,%2,%3}, {%4,%5,%6,%7}, {%8,%9}, {%0,%1,%2,%3};"
        : "+f"(c[0]), "+f"(c[1]), "+f"(c[2]), "+f"(c[3])
        : "r"(a0), "r"(a1), "r"(a2), "r"(a3), "r"(b0), "r"(b1));
}

__device__ __forceinline__ void ldm_x4(uint32_t* r, uint32_t addr) {
    asm volatile("ldmatrix.sync.aligned.m8n8.x4.shared.b16 {%0,%1,%2,%3}, [%4];"
                 : "=r"(r[0]), "=r"(r[1]), "=r"(r[2]), "=r"(r[3]) : "r"(addr));
}
__device__ __forceinline__ void ldm_x4t(uint32_t* r, uint32_t addr) {
    asm volatile("ldmatrix.sync.aligned.m8n8.x4.trans.shared.b16 {%0,%1,%2,%3}, [%4];"
                 : "=r"(r[0]), "=r"(r[1]), "=r"(r[2]), "=r"(r[3]) : "r"(addr));
}

__device__ __forceinline__ uint32_t smem_u32(const void* p) {
    uint32_t a;
    asm("{ .reg .u64 t; cvta.to.shared.u64 t, %1; cvt.u32.u64 %0, t; }" : "=r"(a) : "l"(p));
    return a;
}
__device__ __forceinline__ void cpasync16(uint32_t dst, const void* src) {
    asm volatile("cp.async.cg.shared.global [%0], [%1], 16;" :: "r"(dst), "l"(src));
}
__device__ __forceinline__ void cp_commit() { asm volatile("cp.async.commit_group;"); }

// ---------------- pack kernels ----------------
__global__ __launch_bounds__(256)
void pack_wqkv_kernel(const float* __restrict__ Wq, const float* __restrict__ Wk,
                      const float* __restrict__ Wv) {
    __shared__ float sm[32][33];
    const int tx = threadIdx.x, ty = threadIdx.y;
    const int mt = blockIdx.x, dt = blockIdx.y;
    const int wh = blockIdx.z;
    const int which = wh >> 4, h = wh & 15;
    const float* W = (which == 0) ? Wq : (which == 1) ? Wk : Wv;
    const float* base = W + h * (D_MODEL * D_HEAD);
#pragma unroll
    for (int i = 0; i < 4; i++) {
        int m = mt * 32 + ty + i * 8;
        sm[ty + i * 8][tx] = base[m * 64 + dt * 32 + tx];
    }
    __syncthreads();
#pragma unroll
    for (int i = 0; i < 4; i++) {
        int dl = ty + i * 8;
        int n = which * 1024 + h * 64 + dt * 32 + dl;
        g_wt[(size_t)n * D_MODEL + mt * 32 + tx] = __float2half_rn(sm[tx][dl]);
    }
}

__global__ __launch_bounds__(256)
void pack_wo_kernel(const float* __restrict__ Wo) {
    __shared__ float sm[32][33];
    const int tx = threadIdx.x, ty = threadIdx.y;
    const int kt = blockIdx.x, nt = blockIdx.y;
#pragma unroll
    for (int i = 0; i < 4; i++) {
        int k = kt * 32 + ty + i * 8;
        sm[ty + i * 8][tx] = Wo[(size_t)k * 1024 + nt * 32 + tx];
    }
    __syncthreads();
#pragma unroll
    for (int i = 0; i < 4; i++) {
        int nl = ty + i * 8;
        g_wo[(size_t)(nt * 32 + nl) * 1024 + kt * 32 + tx] = __float2half_rn(sm[tx][nl]);
    }
}

__global__ void pack_bias_kernel(const float* __restrict__ bq,
                                 const float* __restrict__ bk,
                                 const float* __restrict__ bv) {
    int i = blockIdx.x * 256 + threadIdx.x;
    if (i >= QKV_N) return;
    float v;
    if (i < 1024) v = bq[i];
    else if (i < 2048) v = bk[i - 1024];
    else v = bv[i - 2048];
    g_bias[i] = v;
}

__global__ void x_to_half_kernel(const float* __restrict__ x) {
    int idx = blockIdx.x * 256 + threadIdx.x;      // 16 elems/thread
#pragma unroll
    for (int j = 0; j < 4; j++) {
        size_t e = (size_t)idx * 16 + j * 4;
        const float4 v = *(const float4*)(x + e);
        uint2 o;
        o.x = packh2(v.x, v.y);
        o.y = packh2(v.z, v.w);
        *(uint2*)(g_xh + e) = o;
    }
}

// ---------------- fp16 GEMM, ldmatrix + 3-stage cp.async ----------------
// C[M,N] = A[M,K] * Bt[N,K]^T + bias.  TBM=TBN=128, TBK=64, SW128 swizzle.
#define GA3(s) ((s) * 16384)
#define GB3(s) (49152 + (s) * 16384)
#define G_SMEM 98304

__global__ __launch_bounds__(256, 2)
void h16_gemm(const __half* __restrict__ A, const __half* __restrict__ Bt,
              void* __restrict__ Cout, const float* __restrict__ bias,
              int M, int N, int K, int out_half) {
    extern __shared__ char smg[];
    const uint32_t sb = smem_u32(smg);
    const int tid  = threadIdx.x;
    const int lane = tid & 31;
    const int warp = tid >> 5;
    const int gid  = lane >> 2;
    const int tig  = lane & 3;
    const int wm   = (warp >> 2) * 64;
    const int wn   = (warp & 3) * 32;
    const int br   = blockIdx.y, bc = blockIdx.x;

    const __half* Ab = A  + (size_t)br * 128 * K;
    const __half* Bb = Bt + (size_t)bc * 128 * K;

    auto load_tile = [&](int kt, int buf) {
        const int k0 = kt * 64;
#pragma unroll
        for (int i = 0; i < 4; i++) {
            int c = i * 256 + tid;
            int row = c >> 3, ch = c & 7;
            uint32_t d = row * 128 + ((ch * 16) ^ ((row & 7) << 4));
            cpasync16(sb + GA3(buf) + d, Ab + (size_t)row * K + k0 + ch * 8);
        }
#pragma unroll
        for (int i = 0; i < 4; i++) {
            int c = i * 256 + tid;
            int row = c >> 3, ch = c & 7;
            uint32_t d = row * 128 + ((ch * 16) ^ ((row & 7) << 4));
            cpasync16(sb + GB3(buf) + d, Bb + (size_t)row * K + k0 + ch * 8);
        }
        cp_commit();
    };

    float acc[4][4][4];
#pragma unroll
    for (int mt = 0; mt < 4; mt++)
#pragma unroll
        for (int nt = 0; nt < 4; nt++)
#pragma unroll
            for (int e = 0; e < 4; e++) acc[mt][nt][e] = 0.f;

    // ldmatrix lane-address components
    const uint32_t xr   = (uint32_t)(lane & 7) << 4;
    const uint32_t a_ro = (uint32_t)(lane & 15) * 128;          // A rows 0-15
    const uint32_t a_cs = (uint32_t)(lane >> 4) * 16;           // A chunk (k+8)
    const uint32_t b_ro = (uint32_t)((((lane >> 4) & 1) << 3) + (lane & 7)) * 128;
    const uint32_t b_cs = (uint32_t)((lane >> 3) & 1) * 16;

    const int NT = K / 64;
    load_tile(0, 0);
    if (NT > 1) load_tile(1, 1);

    for (int t = 0; t < NT; t++) {
        if (t + 1 < NT) asm volatile("cp.async.wait_group 1;" ::: "memory");
        else            asm volatile("cp.async.wait_group 0;" ::: "memory");
        __syncthreads();
        if (t + 2 < NT) load_tile(t + 2, (t + 2) % 3);

        const int s = t % 3;
        const uint32_t aB = sb + GA3(s);
        const uint32_t bB = sb + GB3(s);

#pragma unroll
        for (int ks = 0; ks < 4; ks++) {
            const uint32_t ca = (uint32_t)(ks * 32 + a_cs) ^ xr;
            const uint32_t cb = (uint32_t)(ks * 32 + b_cs) ^ xr;
            uint32_t af[4][4], bf[4][2];
#pragma unroll
            for (int mt = 0; mt < 4; mt++)
                ldm_x4(af[mt], aB + (uint32_t)(wm + mt * 16) * 128 + a_ro + ca);
#pragma unroll
            for (int p = 0; p < 2; p++) {
                uint32_t r[4];
                ldm_x4(r, bB + (uint32_t)(wn + p * 16) * 128 + b_ro + cb);
                bf[2 * p][0] = r[0]; bf[2 * p][1] = r[1];
                bf[2 * p + 1][0] = r[2]; bf[2 * p + 1][1] = r[3];
            }
#pragma unroll
            for (int mt = 0; mt < 4; mt++)
#pragma unroll
                for (int nt = 0; nt < 4; nt++)
                    mma_f16(acc[mt][nt], af[mt][0], af[mt][1], af[mt][2], af[mt][3],
                            bf[nt][0], bf[nt][1]);
        }
        __syncthreads();
    }

    // epilogue
#pragma unroll
    for (int mt = 0; mt < 4; mt++) {
        size_t r0 = (size_t)br * 128 + wm + mt * 16 + gid;
        size_t r1 = r0 + 8;
#pragma unroll
        for (int nt = 0; nt < 4; nt++) {
            int col = bc * 128 + wn + nt * 8 + 2 * tig;
            float b0v = bias[col], b1v = bias[col + 1];
            float v00 = acc[mt][nt][0] + b0v, v01 = acc[mt][nt][1] + b1v;
            float v10 = acc[mt][nt][2] + b0v, v11 = acc[mt][nt][3] + b1v;
            if (out_half) {
                __half* C = (__half*)Cout;
                *(uint32_t*)(C + r0 * N + col) = packh2(v00, v01);
                *(uint32_t*)(C + r1 * N + col) = packh2(v10, v11);
            } else {
                float* C = (float*)Cout;
                *(float2*)(C + r0 * N + col) = make_float2(v00, v01);
                *(float2*)(C + r1 * N + col) = make_float2(v10, v11);
            }
        }
    }
}

// ---------------- fp16 flash attention (causal), ldmatrix ----------------
#define FQ    0
#define FK(s) (16384 + (s) * 8192)
#define FV(s) (32768 + (s) * 8192)
#define F_SMEM 49152

__global__ __launch_bounds__(256, 2)
void flash_h16_kernel(const __half* __restrict__ qkv, __half* __restrict__ z) {
    extern __shared__ char smf[];
    const uint32_t sb = smem_u32(smf);

    const int tid  = threadIdx.x;
    const int lane = tid & 31;
    const int warp = tid >> 5;
    const int gid  = lane >> 2;
    const int tig  = lane & 3;
    const int qb = gridDim.x - 1 - blockIdx.x;     // heavy blocks first
    const int h = blockIdx.y, b = blockIdx.z;

    const __half* base = qkv + (size_t)b * SEQ * QKV_N + h * D_HEAD;
    const __half* qptr = base + (size_t)qb * 128 * QKV_N;

    auto load_kv = [&](int jb, int buf) {
        const __half* kp = base + (size_t)jb * 64 * QKV_N + 1024;
        const __half* vp = kp + 1024;
#pragma unroll
        for (int i = 0; i < 2; i++) {
            int c = i * 256 + tid;
            int r = c >> 3, ch = c & 7;
            uint32_t d = r * 128 + ((ch * 16) ^ ((r & 7) << 4));
            cpasync16(sb + FK(buf) + d, kp + (size_t)r * QKV_N + ch * 8);
            cpasync16(sb + FV(buf) + d, vp + (size_t)r * QKV_N + ch * 8);
        }
        cp_commit();
    };

    {   // Q + KV0
#pragma unroll
        for (int i = 0; i < 4; i++) {
            int c = i * 256 + tid;
            int r = c >> 3, ch = c & 7;
            uint32_t d = r * 128 + ((ch * 16) ^ ((r & 7) << 4));
            cpasync16(sb + FQ + d, qptr + (size_t)r * QKV_N + ch * 8);
        }
        load_kv(0, 0);
    }

    float o[8][4];
#pragma unroll
    for (int nt = 0; nt < 8; nt++)
#pragma unroll
        for (int e = 0; e < 4; e++) o[nt][e] = 0.f;
    float mrun0 = -1e30f, mrun1 = -1e30f, lrun0 = 0.f, lrun1 = 0.f;

    const int wrow = warp * 16;
    const int grow = qb * 128 + wrow;
    const int jbmax = 2 * qb + 1;

    // ldmatrix address components
    const uint32_t xr   = (uint32_t)(lane & 7) << 4;
    const uint32_t a_ro = (uint32_t)(wrow + (lane & 15)) * 128;          // Q rows
    const uint32_t a_cs = (uint32_t)(lane >> 4) * 16;
    const uint32_t b_ro = (uint32_t)((((lane >> 4) & 1) << 3) + (lane & 7)) * 128;  // K rows
    const uint32_t b_cs = (uint32_t)((lane >> 3) & 1) * 16;
    // V (trans): matrices must be (k0-7,+0),(k8-15,+0),(k0-7,+16B),(k8-15,+16B)
    const uint32_t v_ro = (uint32_t)((((lane >> 3) & 1) << 3) + (lane & 7)) * 128;
    const uint32_t v_cs = (uint32_t)(lane >> 4) * 16;

    for (int jb = 0; jb <= jbmax; jb++) {
        const int s = jb & 1;
        if (jb + 1 <= jbmax) {
            load_kv(jb + 1, s ^ 1);
            asm volatile("cp.async.wait_group 1;" ::: "memory");
        } else {
            asm volatile("cp.async.wait_group 0;" ::: "memory");
        }
        __syncthreads();

        if (jb * 64 <= grow + 15) {
            const uint32_t qB = sb + FQ;
            const uint32_t kB = sb + FK(s);
            const uint32_t vB = sb + FV(s);

            float sc[8][4];
#pragma unroll
            for (int nt = 0; nt < 8; nt++)
#pragma unroll
                for (int e = 0; e < 4; e++) sc[nt][e] = 0.f;

            // S = Q K^T
#pragma unroll
            for (int ks = 0; ks < 4; ks++) {
                const uint32_t ca = (uint32_t)(ks * 32 + a_cs) ^ xr;
                const uint32_t cb = (uint32_t)(ks * 32 + b_cs) ^ xr;
                uint32_t aq[4];
                ldm_x4(aq, qB + a_ro + ca);
                uint32_t kf[8][2];
#pragma unroll
                for (int p = 0; p < 4; p++) {
                    uint32_t r[4];
                    ldm_x4(r, kB + (uint32_t)(p * 16) * 128 + b_ro + cb);
                    kf[2 * p][0] = r[0]; kf[2 * p][1] = r[1];
                    kf[2 * p + 1][0] = r[2]; kf[2 * p + 1][1] = r[3];
                }
#pragma unroll
                for (int nt = 0; nt < 8; nt++)
                    mma_f16(sc[nt], aq[0], aq[1], aq[2], aq[3], kf[nt][0], kf[nt][1]);
            }

#pragma unroll
            for (int nt = 0; nt < 8; nt++)
#pragma unroll
                for (int e = 0; e < 4; e++) sc[nt][e] *= 0.125f;

            // causal mask
            const int r0g = grow + gid, r1g = r0g + 8;
            if (jb * 64 + 63 > grow) {
#pragma unroll
                for (int nt = 0; nt < 8; nt++) {
                    int col = jb * 64 + nt * 8 + 2 * tig;
                    if (col     > r0g) sc[nt][0] = -1e30f;
                    if (col + 1 > r0g) sc[nt][1] = -1e30f;
                    if (col     > r1g) sc[nt][2] = -1e30f;
                    if (col + 1 > r1g) sc[nt][3] = -1e30f;
                }
            }

            // online softmax
            float m0 = -1e30f, m1 = -1e30f;
#pragma unroll
            for (int nt = 0; nt < 8; nt++) {
                m0 = fmaxf(m0, fmaxf(sc[nt][0], sc[nt][1]));
                m1 = fmaxf(m1, fmaxf(sc[nt][2], sc[nt][3]));
            }
            m0 = fmaxf(m0, __shfl_xor_sync(0xffffffffu, m0, 1));
            m0 = fmaxf(m0, __shfl_xor_sync(0xffffffffu, m0, 2));
            m1 = fmaxf(m1, __shfl_xor_sync(0xffffffffu, m1, 1));
            m1 = fmaxf(m1, __shfl_xor_sync(0xffffffffu, m1, 2));

            float mn0 = fmaxf(mrun0, m0), mn1 = fmaxf(mrun1, m1);
            float fac0 = __expf(mrun0 - mn0), fac1 = __expf(mrun1 - mn1);
            mrun0 = mn0; mrun1 = mn1;

            float ls0 = 0.f, ls1 = 0.f;
#pragma unroll
            for (int nt = 0; nt < 8; nt++) {
                sc[nt][0] = __expf(sc[nt][0] - mn0);
                sc[nt][1] = __expf(sc[nt][1] - mn0);
                sc[nt][2] = __expf(sc[nt][2] - mn1);
                sc[nt][3] = __expf(sc[nt][3] - mn1);
                ls0 += sc[nt][0] + sc[nt][1];
                ls1 += sc[nt][2] + sc[nt][3];
            }
            ls0 += __shfl_xor_sync(0xffffffffu, ls0, 1);
            ls0 += __shfl_xor_sync(0xffffffffu, ls0, 2);
            ls1 += __shfl_xor_sync(0xffffffffu, ls1, 1);
            ls1 += __shfl_xor_sync(0xffffffffu, ls1, 2);
            lrun0 = lrun0 * fac0 + ls0;
            lrun1 = lrun1 * fac1 + ls1;

#pragma unroll
            for (int nt = 0; nt < 8; nt++) {
                o[nt][0] *= fac0; o[nt][1] *= fac0;
                o[nt][2] *= fac1; o[nt][3] *= fac1;
            }

            // O += P V  (P from C-fragments; V via ldmatrix.trans)
#pragma unroll
            for (int ks = 0; ks < 4; ks++) {
                uint32_t a0 = packh2(sc[2 * ks][0],     sc[2 * ks][1]);
                uint32_t a1 = packh2(sc[2 * ks][2],     sc[2 * ks][3]);
                uint32_t a2 = packh2(sc[2 * ks + 1][0], sc[2 * ks + 1][1]);
                uint32_t a3 = packh2(sc[2 * ks + 1][2], sc[2 * ks + 1][3]);
                const uint32_t vkb = vB + (uint32_t)(ks * 16) * 128 + v_ro;
#pragma unroll
                for (int p = 0; p < 4; p++) {
                    uint32_t r[4];
                    ldm_x4t(r, vkb + ((uint32_t)(p * 32 + v_cs) ^ xr));
                    mma_f16(o[2 * p],     a0, a1, a2, a3, r[0], r[1]);
                    mma_f16(o[2 * p + 1], a0, a1, a2, a3, r[2], r[3]);
                }
            }
        }
        __syncthreads();
    }

    // epilogue: z half
    float il0 = 1.0f / lrun0, il1 = 1.0f / lrun1;
    size_t r0 = (size_t)b * SEQ + grow + gid;
    size_t r1 = r0 + 8;
#pragma unroll
    for (int nt = 0; nt < 8; nt++) {
        int col = h * D_HEAD + nt * 8 + 2 * tig;
        *(uint32_t*)(z + r0 * D_MODEL + col) = packh2(o[nt][0] * il0, o[nt][1] * il0);
        *(uint32_t*)(z + r1 * D_MODEL + col) = packh2(o[nt][2] * il1, o[nt][3] * il1);
    }
}

// ---------------- launch ----------------
extern "C" void kernel_launch(void* const* d_in, const int* in_sizes, int n_in,
                              void* d_out, int out_size) {
    const float* x  = (const float*)d_in[0];
    const float* Wq = (const float*)d_in[1];
    const float* Wk = (const float*)d_in[2];
    const float* Wv = (const float*)d_in[3];
    const float* Wo = (const float*)d_in[4];
    const float* bq = (const float*)d_in[5];
    const float* bk = (const float*)d_in[6];
    const float* bv = (const float*)d_in[7];
    const float* bo = (const float*)d_in[8];
    float* out = (float*)d_out;

    __half *wt, *wo, *xh, *qkv, *zh;
    float *bias;
    cudaGetSymbolAddress((void**)&wt,   g_wt);
    cudaGetSymbolAddress((void**)&wo,   g_wo);
    cudaGetSymbolAddress((void**)&bias, g_bias);
    cudaGetSymbolAddress((void**)&xh,   g_xh);
    cudaGetSymbolAddress((void**)&qkv,  g_qkv);
    cudaGetSymbolAddress((void**)&zh,   g_zh);

    {   // packs
        dim3 blk(32, 8);
        pack_wqkv_kernel<<<dim3(32, 2, 48), blk>>>(Wq, Wk, Wv);
        pack_wo_kernel<<<dim3(32, 32), blk>>>(Wo);
        pack_bias_kernel<<<(QKV_N + 255) / 256, 256>>>(bq, bk, bv);
        x_to_half_kernel<<<(ROWS * D_MODEL / 16 + 255) / 256, 256>>>(x);
    }

    cudaFuncSetAttribute(h16_gemm, cudaFuncAttributeMaxDynamicSharedMemorySize, G_SMEM);
    cudaFuncSetAttribute(flash_h16_kernel, cudaFuncAttributeMaxDynamicSharedMemorySize, F_SMEM);

    {   // QKV projection -> half qkv
        dim3 grid(QKV_N / 128, ROWS / 128);
        h16_gemm<<<grid, 256, G_SMEM>>>(xh, wt, qkv, bias, ROWS, QKV_N, D_MODEL, 1);
    }

    {   // flash attention -> half z
        dim3 grid(SEQ / 128, N_HEADS, BATCH);
        flash_h16_kernel<<<grid, 256, F_SMEM>>>(qkv, zh);
    }

    {   // output projection -> fp32 out
        dim3 grid(D_MODEL / 128, ROWS / 128);
        h16_gemm<<<grid, 256, G_SMEM>>>(zh, wo, out, bo, ROWS, D_MODEL, D_MODEL, 0);
    }
}